// round 2
// baseline (speedup 1.0000x reference)
#include <cuda_runtime.h>
#include <math.h>

#define EMB 64
#define NLAYERS 2
#define NUx 100000
#define NIx 50000
#define ERx 1000000
#define ETx 800000
#define EPx 200000
#define HALL 192   // EMB*(1+L)

// ---------------- static scratch (no allocations allowed) ----------------
__device__ float g_hu_all[(size_t)NUx * HALL];
__device__ float g_hi_all[(size_t)NIx * HALL];
__device__ float g_fs[(size_t)NUx * EMB];
__device__ float g_fd[(size_t)NUx * EMB];
__device__ float g_agg[(size_t)NUx * EMB];
__device__ float g_denom[NUx];
__device__ float g_ebuf[ERx];
__device__ float g_p[(size_t)NUx * EMB];
__device__ float g_q[(size_t)NUx * EMB];
__device__ float g_zinf[NUx];
__device__ float g_zint[NUx];
__device__ float g_gate[264];   // [2][132]: v[128], c at 128
__device__ float g_sums[4];     // s_inf, ss_inf, s_int, ss_int

// ---------------- kernels ----------------

__global__ void copy_block(const float* __restrict__ src, float* __restrict__ dst,
                           int dstride, int n64) {
    int i = blockIdx.x * blockDim.x + threadIdx.x;
    if (i >= n64) return;
    int row = i >> 6, j = i & 63;
    dst[(size_t)row * dstride + j] = src[i];
}

// Y[row, 0:64] = X[row, 0:64] @ W[64x64] + B,  X row-stride = xstride, Y row-stride = ystride
__global__ void gemm64(const float* __restrict__ X, int xstride,
                       const float* __restrict__ W, const float* __restrict__ Bv,
                       float* __restrict__ Y, int ystride, int n) {
    __shared__ float sW[64 * 64];
    __shared__ float sX[16 * 68];
    int tx = threadIdx.x;
    for (int i = tx; i < 4096; i += 256) sW[i] = W[i];
    int row0 = blockIdx.x * 16;
    for (int i = tx; i < 1024; i += 256) {
        int r = i >> 6, k = i & 63;
        int row = row0 + r;
        sX[r * 68 + k] = (row < n) ? X[(size_t)row * xstride + k] : 0.f;
    }
    __syncthreads();
    int c = tx & 15;   // 4 columns: 4c..4c+3
    int r = tx >> 4;   // row within block tile
    int row = row0 + r;
    if (row >= n) return;
    float4 acc = *(const float4*)(Bv + 4 * c);
    const float4* sW4 = (const float4*)sW;
    const float* xr = sX + r * 68;
#pragma unroll
    for (int k = 0; k < 64; k++) {
        float xv = xr[k];
        float4 w4 = sW4[k * 16 + c];
        acc.x += xv * w4.x; acc.y += xv * w4.y;
        acc.z += xv * w4.z; acc.w += xv * w4.w;
    }
    *(float4*)(Y + (size_t)row * ystride + 4 * c) = acc;
}

// Per edge: ex = exp( attn . leaky_relu(fs[src]+fd[dst], 0.2) ); atomic denom[dst] += ex
__global__ void edge_pass1(const int* __restrict__ src, const int* __restrict__ dst,
                           const float* __restrict__ fs, const float* __restrict__ fd,
                           const float* __restrict__ attn,
                           float* __restrict__ ebuf, float* __restrict__ denom, int E) {
    int w = (blockIdx.x * blockDim.x + threadIdx.x) >> 5;
    int lane = threadIdx.x & 31;
    if (w >= E) return;
    int s = src[w], d = dst[w];
    float2 a = ((const float2*)(fs + (size_t)s * 64))[lane];
    float2 b = ((const float2*)(fd + (size_t)d * 64))[lane];
    float2 t = ((const float2*)attn)[lane];
    float x0 = a.x + b.x, x1 = a.y + b.y;
    x0 = x0 > 0.f ? x0 : 0.2f * x0;
    x1 = x1 > 0.f ? x1 : 0.2f * x1;
    float e = x0 * t.x + x1 * t.y;
#pragma unroll
    for (int off = 16; off; off >>= 1) e += __shfl_down_sync(0xffffffffu, e, off);
    if (lane == 0) {
        float ex = expf(e);
        ebuf[w] = ex;
        atomicAdd(denom + d, ex);
    }
}

// Per edge: alpha = ex/denom[dst]; agg[dst] += alpha * fs[src]  (red.v4)
__global__ void edge_pass2(const int* __restrict__ src, const int* __restrict__ dst,
                           const float* __restrict__ fs, const float* __restrict__ ebuf,
                           const float* __restrict__ denom, float* __restrict__ agg, int E) {
    int g = (blockIdx.x * blockDim.x + threadIdx.x) >> 4;
    int lane = threadIdx.x & 15;
    if (g >= E) return;
    int s = src[g], d = dst[g];
    float alpha = ebuf[g] / denom[d];
    float4 v = ((const float4*)(fs + (size_t)s * 64))[lane];
    float* ap = agg + (size_t)d * 64 + lane * 4;
    asm volatile("red.global.add.v4.f32 [%0], {%1,%2,%3,%4};"
                 :: "l"(ap), "f"(v.x * alpha), "f"(v.y * alpha),
                    "f"(v.z * alpha), "f"(v.w * alpha) : "memory");
}

// out[row] = agg[row] + bias (+ resid[row])
__global__ void finish_kernel(const float* __restrict__ agg, const float* __restrict__ bias,
                              const float* __restrict__ resid, int rstride,
                              float* __restrict__ out, int ostride, int n) {
    int i = blockIdx.x * blockDim.x + threadIdx.x;
    if (i >= n * 64) return;
    int row = i >> 6, j = i & 63;
    float v = agg[i] + bias[j];
    if (resid) v += resid[(size_t)row * rstride + j];
    out[(size_t)row * ostride + j] = v;
}

// collapse gate MLP: v[k] = sum_j W1[k][j]*W2[j];  c = b1.W2 + b2
__global__ void gate_prep(const float* __restrict__ W1, const float* __restrict__ b1,
                          const float* __restrict__ W2, const float* __restrict__ b2,
                          float* __restrict__ gout) {
    int t = threadIdx.x;          // 256
    int i = t >> 7, k = t & 127;
    const float* w1 = W1 + (size_t)i * 128 * 128 + (size_t)k * 128;
    const float* w2 = W2 + i * 128;
    float v = 0.f;
    for (int j = 0; j < 128; j++) v += w1[j] * w2[j];
    gout[i * 132 + k] = v;
    if (k == 0) {
        float c = b2[i];
        const float* bb = b1 + i * 128;
        for (int j = 0; j < 128; j++) c += bb[j] * w2[j];
        gout[i * 132 + 128] = c;
    }
}

// z_inf = [hu,p].v_inf + c ; z_int = [hu,q].v_int + c ; accumulate BN stats
__global__ void z_kernel(const float* __restrict__ HU, const float* __restrict__ p,
                         const float* __restrict__ q, const float* __restrict__ gate,
                         float* __restrict__ zinf, float* __restrict__ zint,
                         float* __restrict__ sums, int n) {
    __shared__ float red[8][4];
    int w = (blockIdx.x * blockDim.x + threadIdx.x) >> 5;
    int wl = threadIdx.x >> 5;
    int lane = threadIdx.x & 31;
    float zi = 0.f, zt = 0.f;
    if (w < n) {
        float2 h  = ((const float2*)(HU + (size_t)w * HALL))[lane];
        float2 pv = ((const float2*)(p  + (size_t)w * 64))[lane];
        float2 qv = ((const float2*)(q  + (size_t)w * 64))[lane];
        const float2* vinf = (const float2*)gate;
        const float2* vint = (const float2*)(gate + 132);
        float2 vi0 = vinf[lane], vi1 = vinf[32 + lane];
        float2 vt0 = vint[lane], vt1 = vint[32 + lane];
        zi = h.x * vi0.x + h.y * vi0.y + pv.x * vi1.x + pv.y * vi1.y;
        zt = h.x * vt0.x + h.y * vt0.y + qv.x * vt1.x + qv.y * vt1.y;
    }
#pragma unroll
    for (int off = 16; off; off >>= 1) {
        zi += __shfl_down_sync(0xffffffffu, zi, off);
        zt += __shfl_down_sync(0xffffffffu, zt, off);
    }
    if (lane == 0) {
        if (w < n) {
            zi += gate[128]; zt += gate[132 + 128];
            zinf[w] = zi; zint[w] = zt;
            red[wl][0] = zi; red[wl][1] = zi * zi;
            red[wl][2] = zt; red[wl][3] = zt * zt;
        } else {
            red[wl][0] = red[wl][1] = red[wl][2] = red[wl][3] = 0.f;
        }
    }
    __syncthreads();
    if (threadIdx.x < 4) {
        float s = 0.f;
        for (int k = 0; k < 8; k++) s += red[k][threadIdx.x];
        atomicAdd(sums + threadIdx.x, s);
    }
}

// BN + leaky(0.01) + softmax gate; HUo = g0*p + g1*q + HU
__global__ void gate_apply(const float* __restrict__ HU, float* __restrict__ HUo,
                           const float* __restrict__ p, const float* __restrict__ q,
                           const float* __restrict__ zinf, const float* __restrict__ zint,
                           const float* __restrict__ sums, int n) {
    int w = (blockIdx.x * blockDim.x + threadIdx.x) >> 5;
    int lane = threadIdx.x & 31;
    if (w >= n) return;
    float inv = 1.0f / (float)n;
    float mu0 = sums[0] * inv;
    float var0 = sums[1] * inv - mu0 * mu0;
    float mu1 = sums[2] * inv;
    float var1 = sums[3] * inv - mu1 * mu1;
    float a0 = (zinf[w] - mu0) * rsqrtf(var0 + 1e-5f);
    float a1 = (zint[w] - mu1) * rsqrtf(var1 + 1e-5f);
    a0 = a0 > 0.f ? a0 : 0.01f * a0;
    a1 = a1 > 0.f ? a1 : 0.01f * a1;
    float m = fmaxf(a0, a1);
    float e0 = expf(a0 - m), e1 = expf(a1 - m);
    float g0 = e0 / (e0 + e1), g1 = e1 / (e0 + e1);
    float2 pv = ((const float2*)(p + (size_t)w * 64))[lane];
    float2 qv = ((const float2*)(q + (size_t)w * 64))[lane];
    float2 hv = ((const float2*)(HU + (size_t)w * HALL))[lane];
    float2 o;
    o.x = g0 * pv.x + g1 * qv.x + hv.x;
    o.y = g0 * pv.y + g1 * qv.y + hv.y;
    ((float2*)(HUo + (size_t)w * HALL))[lane] = o;
}

__global__ void pair_kernel(const int* __restrict__ uu, const int* __restrict__ ii,
                            const float* __restrict__ hu_all, const float* __restrict__ hi_all,
                            float* __restrict__ out, int np) {
    int w = (blockIdx.x * blockDim.x + threadIdx.x) >> 5;
    int lane = threadIdx.x & 31;
    if (w >= np) return;
    const float* hr = hu_all + (size_t)uu[w] * HALL;
    const float* ir = hi_all + (size_t)ii[w] * HALL;
    float s = 0.f;
#pragma unroll
    for (int c = 0; c < 6; c++) s += hr[lane + 32 * c] * ir[lane + 32 * c];
#pragma unroll
    for (int off = 16; off; off >>= 1) s += __shfl_down_sync(0xffffffffu, s, off);
    if (lane == 0) out[w] = s;
}

// ---------------- host ----------------

static float* sym_addr(const void* s) {
    void* p = nullptr;
    cudaGetSymbolAddress(&p, s);
    return (float*)p;
}

static void run_gat(const float* hs, int hs_stride, int ns,
                    const float* hd, int hd_stride, int nd,
                    const int* src, const int* dst, int E,
                    const float* W, const float* B, const float* attn, const float* bias,
                    const float* resid, int rstride, float* out, int ostride,
                    float* fs, float* fd, float* agg, float* denom, float* ebuf) {
    gemm64<<<(ns + 15) / 16, 256>>>(hs, hs_stride, W, B, fs, 64, ns);
    gemm64<<<(nd + 15) / 16, 256>>>(hd, hd_stride, W + 4096, B + 64, fd, 64, nd);
    cudaMemsetAsync(denom, 0, (size_t)nd * sizeof(float));
    cudaMemsetAsync(agg, 0, (size_t)nd * 64 * sizeof(float));
    edge_pass1<<<(E + 7) / 8, 256>>>(src, dst, fs, fd, attn, ebuf, denom, E);
    edge_pass2<<<(E + 15) / 16, 256>>>(src, dst, fs, ebuf, denom, agg, E);
    finish_kernel<<<(nd * 64 + 255) / 256, 256>>>(agg, bias, resid, rstride, out, ostride, nd);
}

extern "C" void kernel_launch(void* const* d_in, const int* in_sizes, int n_in,
                              void* d_out, int out_size) {
    // Locate anchors in in_sizes (robust to either metadata ordering).
    int wf = -1, gf = -1;
    for (int i = 0; i < n_in; i++) {
        if (wf < 0 && in_sizes[i] == NUx * EMB) wf = i;   // eu
        if (gf < 0 && in_sizes[i] == ERx) gf = i;         // rate_src
    }
    if (wf < 0) wf = 0;
    if (gf < 0) gf = (wf == 0) ? 18 : 0;
    const float* eu        = (const float*)d_in[wf + 0];
    const float* ei        = (const float*)d_in[wf + 1];
    const float* rate_W    = (const float*)d_in[wf + 2];
    const float* rate_b    = (const float*)d_in[wf + 3];
    const float* rate_attn = (const float*)d_in[wf + 4];
    const float* rate_bias = (const float*)d_in[wf + 5];
    const float* rb_W      = (const float*)d_in[wf + 6];
    const float* rb_b      = (const float*)d_in[wf + 7];
    const float* rb_attn   = (const float*)d_in[wf + 8];
    const float* rb_bias   = (const float*)d_in[wf + 9];
    const float* tr_W      = (const float*)d_in[wf + 10];
    const float* tr_b      = (const float*)d_in[wf + 11];
    const float* tr_attn   = (const float*)d_in[wf + 12];
    const float* tr_bias   = (const float*)d_in[wf + 13];
    const float* attW1     = (const float*)d_in[wf + 14];
    const float* attb1     = (const float*)d_in[wf + 15];
    const float* attW2     = (const float*)d_in[wf + 16];
    const float* attb2     = (const float*)d_in[wf + 17];
    const int* rate_src  = (const int*)d_in[gf + 0];
    const int* rate_dst  = (const int*)d_in[gf + 1];
    const int* trust_src = (const int*)d_in[gf + 2];
    const int* trust_dst = (const int*)d_in[gf + 3];
    const int* pos_u     = (const int*)d_in[gf + 4];
    const int* pos_i     = (const int*)d_in[gf + 5];
    const int* neg_u     = (const int*)d_in[gf + 6];
    const int* neg_i     = (const int*)d_in[gf + 7];

    float* hu_all = sym_addr(g_hu_all);
    float* hi_all = sym_addr(g_hi_all);
    float* fs     = sym_addr(g_fs);
    float* fd     = sym_addr(g_fd);
    float* agg    = sym_addr(g_agg);
    float* denom  = sym_addr(g_denom);
    float* ebuf   = sym_addr(g_ebuf);
    float* pbuf   = sym_addr(g_p);
    float* qbuf   = sym_addr(g_q);
    float* zinf   = sym_addr(g_zinf);
    float* zint   = sym_addr(g_zint);
    float* gate   = sym_addr(g_gate);
    float* sums   = sym_addr(g_sums);
    float* out    = (float*)d_out;

    // hu_all[:,0:64] = eu ; hi_all[:,0:64] = ei
    copy_block<<<(NUx * 64 + 255) / 256, 256>>>(eu, hu_all, HALL, NUx * 64);
    copy_block<<<(NIx * 64 + 255) / 256, 256>>>(ei, hi_all, HALL, NIx * 64);

    for (int l = 0; l < NLAYERS; l++) {
        const float* HU = hu_all + l * 64;        // stride HALL
        float* HUo      = hu_all + (l + 1) * 64;
        const float* HI = hi_all + l * 64;
        float* HIo      = hi_all + (l + 1) * 64;

        // rate: user -> item, residual + bias, write to HIo
        run_gat(HU, HALL, NUx, HI, HALL, NIx, rate_src, rate_dst, ERx,
                rate_W + (size_t)l * 2 * 4096, rate_b + (size_t)l * 2 * 64,
                rate_attn + l * 64, rate_bias + l * 64,
                HI, HALL, HIo, HALL, fs, fd, agg, denom, ebuf);

        // rated-by: item -> user (reversed edges), write q
        run_gat(HI, HALL, NIx, HU, HALL, NUx, rate_dst, rate_src, ERx,
                rb_W + (size_t)l * 2 * 4096, rb_b + (size_t)l * 2 * 64,
                rb_attn + l * 64, rb_bias + l * 64,
                nullptr, 0, qbuf, 64, fs, fd, agg, denom, ebuf);

        // trust: user -> user, write p
        run_gat(HU, HALL, NUx, HU, HALL, NUx, trust_src, trust_dst, ETx,
                tr_W + (size_t)l * 2 * 4096, tr_b + (size_t)l * 2 * 64,
                tr_attn + l * 64, tr_bias + l * 64,
                nullptr, 0, pbuf, 64, fs, fd, agg, denom, ebuf);

        // gates
        gate_prep<<<1, 256>>>(attW1 + (size_t)l * 2 * 128 * 128,
                              attb1 + (size_t)l * 2 * 128,
                              attW2 + (size_t)l * 2 * 128,
                              attb2 + (size_t)l * 2, gate);
        cudaMemsetAsync(sums, 0, 4 * sizeof(float));
        z_kernel<<<(NUx + 7) / 8, 256>>>(HU, pbuf, qbuf, gate, zinf, zint, sums, NUx);
        gate_apply<<<(NUx + 7) / 8, 256>>>(HU, HUo, pbuf, qbuf, zinf, zint, sums, NUx);
    }

    pair_kernel<<<(EPx + 7) / 8, 256>>>(pos_u, pos_i, hu_all, hi_all, out, EPx);
    pair_kernel<<<(EPx + 7) / 8, 256>>>(neg_u, neg_i, hu_all, hi_all, out + EPx, EPx);
}

// round 3
// speedup vs baseline: 1.4470x; 1.4470x over previous
#include <cuda_runtime.h>
#include <math.h>

#define EMB 64
#define NLAYERS 2
#define NUx 100000
#define NIx 50000
#define ERx 1000000
#define ETx 800000
#define EPx 200000
#define HALL 192   // EMB*(1+L)

// ---------------- static scratch (no allocations allowed) ----------------
__device__ float g_hu_all[(size_t)NUx * HALL];
__device__ float g_hi_all[(size_t)NIx * HALL];
__device__ float g_fs[(size_t)NUx * EMB];
__device__ float g_fd[(size_t)NUx * EMB];
__device__ float g_agg[(size_t)NUx * EMB];
__device__ float g_denom[NUx];
__device__ float g_p[(size_t)NUx * EMB];
__device__ float g_q[(size_t)NUx * EMB];
__device__ float g_zinf[NUx];
__device__ float g_zint[NUx];
__device__ float g_gate[264];   // [2][132]: v[128], c at 128
__device__ float g_sums[4];     // s_inf, ss_inf, s_int, ss_int

// ---------------- kernels ----------------

__global__ void copy_block(const float* __restrict__ src, float* __restrict__ dst,
                           int dstride, int n64) {
    int i = blockIdx.x * blockDim.x + threadIdx.x;
    if (i >= n64) return;
    int row = i >> 6, j = i & 63;
    dst[(size_t)row * dstride + j] = src[i];
}

// Y[row, 0:64] = X[row, 0:64] @ W[64x64] + B.
// 64-row tile per block, 256 threads, each thread computes 4 rows x 4 cols.
// X is transposed into shared so the inner loop is 2 x LDS.128 per 16 FMAs.
__global__ void gemm64v2(const float* __restrict__ X, int xstride,
                         const float* __restrict__ W, const float* __restrict__ Bv,
                         float* __restrict__ Y, int ystride, int n) {
    __shared__ float sW[64 * 64];       // sW[k*64 + c]
    __shared__ float sXT[64 * 68];      // sXT[k*68 + r]
    int tx = threadIdx.x;
    int row0 = blockIdx.x * 64;

    // load W (coalesced float4)
    for (int i = tx; i < 1024; i += 256)
        ((float4*)sW)[i] = ((const float4*)W)[i];

    // load X tile transposed: thread handles row r, 16 consecutive cols
    {
        int r = tx & 63, qu = tx >> 6;   // qu in 0..3 -> cols 16qu..16qu+15
        int row = row0 + r;
        if (row < n) {
            const float4* xr = (const float4*)(X + (size_t)row * xstride);
#pragma unroll
            for (int j = 0; j < 4; j++) {
                float4 v = xr[qu * 4 + j];
                int k = qu * 16 + j * 4;
                sXT[(k + 0) * 68 + r] = v.x;
                sXT[(k + 1) * 68 + r] = v.y;
                sXT[(k + 2) * 68 + r] = v.z;
                sXT[(k + 3) * 68 + r] = v.w;
            }
        } else {
#pragma unroll
            for (int j = 0; j < 4; j++) {
                int k = qu * 16 + j * 4;
                sXT[(k + 0) * 68 + r] = 0.f;
                sXT[(k + 1) * 68 + r] = 0.f;
                sXT[(k + 2) * 68 + r] = 0.f;
                sXT[(k + 3) * 68 + r] = 0.f;
            }
        }
    }
    __syncthreads();

    int ty = tx >> 4;    // rows 4ty..4ty+3
    int c  = tx & 15;    // cols 4c..4c+3
    float4 b0 = *(const float4*)(Bv + 4 * c);
    float4 acc0 = b0, acc1 = b0, acc2 = b0, acc3 = b0;
#pragma unroll
    for (int k = 0; k < 64; k++) {
        float4 w4 = ((const float4*)sW)[k * 16 + c];
        float4 a4 = *(const float4*)(sXT + k * 68 + 4 * ty);
        acc0.x += a4.x * w4.x; acc0.y += a4.x * w4.y; acc0.z += a4.x * w4.z; acc0.w += a4.x * w4.w;
        acc1.x += a4.y * w4.x; acc1.y += a4.y * w4.y; acc1.z += a4.y * w4.z; acc1.w += a4.y * w4.w;
        acc2.x += a4.z * w4.x; acc2.y += a4.z * w4.y; acc2.z += a4.z * w4.z; acc2.w += a4.z * w4.w;
        acc3.x += a4.w * w4.x; acc3.y += a4.w * w4.y; acc3.z += a4.w * w4.z; acc3.w += a4.w * w4.w;
    }
    int rbase = row0 + 4 * ty;
    if (rbase + 0 < n) *(float4*)(Y + (size_t)(rbase + 0) * ystride + 4 * c) = acc0;
    if (rbase + 1 < n) *(float4*)(Y + (size_t)(rbase + 1) * ystride + 4 * c) = acc1;
    if (rbase + 2 < n) *(float4*)(Y + (size_t)(rbase + 2) * ystride + 4 * c) = acc2;
    if (rbase + 3 < n) *(float4*)(Y + (size_t)(rbase + 3) * ystride + 4 * c) = acc3;
}

// Fused edge pass: one warp per edge.
// e = attn . leaky_relu(fs[src]+fd[dst]); ex = exp(e)
// denom[dst] += ex ; agg[dst] += ex * fs[src]   (division deferred to finish)
__global__ void edge_fused(const int* __restrict__ src, const int* __restrict__ dst,
                           const float* __restrict__ fs, const float* __restrict__ fd,
                           const float* __restrict__ attn,
                           float* __restrict__ denom, float* __restrict__ agg, int E) {
    int w = (blockIdx.x * blockDim.x + threadIdx.x) >> 5;
    int lane = threadIdx.x & 31;
    if (w >= E) return;
    int s = src[w], d = dst[w];
    int h = lane & 15;
    bool lo = lane < 16;
    float4 mine = lo ? ((const float4*)(fs + (size_t)s * 64))[h]
                     : ((const float4*)(fd + (size_t)d * 64))[h];
    float4 oth;
    oth.x = __shfl_xor_sync(0xffffffffu, mine.x, 16);
    oth.y = __shfl_xor_sync(0xffffffffu, mine.y, 16);
    oth.z = __shfl_xor_sync(0xffffffffu, mine.z, 16);
    oth.w = __shfl_xor_sync(0xffffffffu, mine.w, 16);
    float4 x;
    x.x = mine.x + oth.x; x.y = mine.y + oth.y;
    x.z = mine.z + oth.z; x.w = mine.w + oth.w;
    x.x = x.x > 0.f ? x.x : 0.2f * x.x;
    x.y = x.y > 0.f ? x.y : 0.2f * x.y;
    x.z = x.z > 0.f ? x.z : 0.2f * x.z;
    x.w = x.w > 0.f ? x.w : 0.2f * x.w;
    float4 t = ((const float4*)attn)[h];
    float p = x.x * t.x + x.y * t.y + x.z * t.z + x.w * t.w;
    // butterfly over 16 lanes: both halves end with the full dot product
#pragma unroll
    for (int off = 8; off; off >>= 1) p += __shfl_xor_sync(0xffffffffu, p, off);
    float ex = expf(p);
    if (lane == 0)
        asm volatile("red.global.add.f32 [%0], %1;" :: "l"(denom + d), "f"(ex) : "memory");
    if (lo) {
        float* ap = agg + (size_t)d * 64 + h * 4;
        asm volatile("red.global.add.v4.f32 [%0], {%1,%2,%3,%4};"
                     :: "l"(ap), "f"(mine.x * ex), "f"(mine.y * ex),
                        "f"(mine.z * ex), "f"(mine.w * ex) : "memory");
    }
}

// out[row] = agg[row]/denom[row] + bias (+ resid[row]); empty segment -> 0 + bias (+resid)
__global__ void finish_kernel(const float* __restrict__ agg, const float* __restrict__ denom,
                              const float* __restrict__ bias,
                              const float* __restrict__ resid, int rstride,
                              float* __restrict__ out, int ostride, int n) {
    int i = blockIdx.x * blockDim.x + threadIdx.x;
    if (i >= n * 64) return;
    int row = i >> 6, j = i & 63;
    float dn = denom[row];
    float v = (dn > 0.f ? agg[i] / dn : 0.f) + bias[j];
    if (resid) v += resid[(size_t)row * rstride + j];
    out[(size_t)row * ostride + j] = v;
}

// collapse gate MLP: v[k] = sum_j W1[k][j]*W2[j];  c = b1.W2 + b2
__global__ void gate_prep(const float* __restrict__ W1, const float* __restrict__ b1,
                          const float* __restrict__ W2, const float* __restrict__ b2,
                          float* __restrict__ gout) {
    int t = threadIdx.x;          // 256
    int i = t >> 7, k = t & 127;
    const float* w1 = W1 + (size_t)i * 128 * 128 + (size_t)k * 128;
    const float* w2 = W2 + i * 128;
    float v = 0.f;
    for (int j = 0; j < 128; j++) v += w1[j] * w2[j];
    gout[i * 132 + k] = v;
    if (k == 0) {
        float c = b2[i];
        const float* bb = b1 + i * 128;
        for (int j = 0; j < 128; j++) c += bb[j] * w2[j];
        gout[i * 132 + 128] = c;
    }
}

// z_inf = [hu,p].v_inf + c ; z_int = [hu,q].v_int + c ; accumulate BN stats
__global__ void z_kernel(const float* __restrict__ HU, const float* __restrict__ p,
                         const float* __restrict__ q, const float* __restrict__ gate,
                         float* __restrict__ zinf, float* __restrict__ zint,
                         float* __restrict__ sums, int n) {
    __shared__ float red[8][4];
    int w = (blockIdx.x * blockDim.x + threadIdx.x) >> 5;
    int wl = threadIdx.x >> 5;
    int lane = threadIdx.x & 31;
    float zi = 0.f, zt = 0.f;
    if (w < n) {
        float2 h  = ((const float2*)(HU + (size_t)w * HALL))[lane];
        float2 pv = ((const float2*)(p  + (size_t)w * 64))[lane];
        float2 qv = ((const float2*)(q  + (size_t)w * 64))[lane];
        const float2* vinf = (const float2*)gate;
        const float2* vint = (const float2*)(gate + 132);
        float2 vi0 = vinf[lane], vi1 = vinf[32 + lane];
        float2 vt0 = vint[lane], vt1 = vint[32 + lane];
        zi = h.x * vi0.x + h.y * vi0.y + pv.x * vi1.x + pv.y * vi1.y;
        zt = h.x * vt0.x + h.y * vt0.y + qv.x * vt1.x + qv.y * vt1.y;
    }
#pragma unroll
    for (int off = 16; off; off >>= 1) {
        zi += __shfl_down_sync(0xffffffffu, zi, off);
        zt += __shfl_down_sync(0xffffffffu, zt, off);
    }
    if (lane == 0) {
        if (w < n) {
            zi += gate[128]; zt += gate[132 + 128];
            zinf[w] = zi; zint[w] = zt;
            red[wl][0] = zi; red[wl][1] = zi * zi;
            red[wl][2] = zt; red[wl][3] = zt * zt;
        } else {
            red[wl][0] = red[wl][1] = red[wl][2] = red[wl][3] = 0.f;
        }
    }
    __syncthreads();
    if (threadIdx.x < 4) {
        float s = 0.f;
        for (int k = 0; k < 8; k++) s += red[k][threadIdx.x];
        atomicAdd(sums + threadIdx.x, s);
    }
}

// BN + leaky(0.01) + softmax gate; HUo = g0*p + g1*q + HU
__global__ void gate_apply(const float* __restrict__ HU, float* __restrict__ HUo,
                           const float* __restrict__ p, const float* __restrict__ q,
                           const float* __restrict__ zinf, const float* __restrict__ zint,
                           const float* __restrict__ sums, int n) {
    int w = (blockIdx.x * blockDim.x + threadIdx.x) >> 5;
    int lane = threadIdx.x & 31;
    if (w >= n) return;
    float inv = 1.0f / (float)n;
    float mu0 = sums[0] * inv;
    float var0 = sums[1] * inv - mu0 * mu0;
    float mu1 = sums[2] * inv;
    float var1 = sums[3] * inv - mu1 * mu1;
    float a0 = (zinf[w] - mu0) * rsqrtf(var0 + 1e-5f);
    float a1 = (zint[w] - mu1) * rsqrtf(var1 + 1e-5f);
    a0 = a0 > 0.f ? a0 : 0.01f * a0;
    a1 = a1 > 0.f ? a1 : 0.01f * a1;
    float m = fmaxf(a0, a1);
    float e0 = expf(a0 - m), e1 = expf(a1 - m);
    float g0 = e0 / (e0 + e1), g1 = e1 / (e0 + e1);
    float2 pv = ((const float2*)(p + (size_t)w * 64))[lane];
    float2 qv = ((const float2*)(q + (size_t)w * 64))[lane];
    float2 hv = ((const float2*)(HU + (size_t)w * HALL))[lane];
    float2 o;
    o.x = g0 * pv.x + g1 * qv.x + hv.x;
    o.y = g0 * pv.y + g1 * qv.y + hv.y;
    ((float2*)(HUo + (size_t)w * HALL))[lane] = o;
}

__global__ void pair_kernel(const int* __restrict__ uu, const int* __restrict__ ii,
                            const float* __restrict__ hu_all, const float* __restrict__ hi_all,
                            float* __restrict__ out, int np) {
    int w = (blockIdx.x * blockDim.x + threadIdx.x) >> 5;
    int lane = threadIdx.x & 31;
    if (w >= np) return;
    const float* hr = hu_all + (size_t)uu[w] * HALL;
    const float* ir = hi_all + (size_t)ii[w] * HALL;
    float s = 0.f;
#pragma unroll
    for (int c = 0; c < 6; c++) s += hr[lane + 32 * c] * ir[lane + 32 * c];
#pragma unroll
    for (int off = 16; off; off >>= 1) s += __shfl_down_sync(0xffffffffu, s, off);
    if (lane == 0) out[w] = s;
}

// ---------------- host ----------------

static float* sym_addr(const void* s) {
    void* p = nullptr;
    cudaGetSymbolAddress(&p, s);
    return (float*)p;
}

static void run_gat(const float* hs, int hs_stride, int ns,
                    const float* hd, int hd_stride, int nd,
                    const int* src, const int* dst, int E,
                    const float* W, const float* B, const float* attn, const float* bias,
                    const float* resid, int rstride, float* out, int ostride,
                    float* fs, float* fd, float* agg, float* denom) {
    gemm64v2<<<(ns + 63) / 64, 256>>>(hs, hs_stride, W, B, fs, 64, ns);
    gemm64v2<<<(nd + 63) / 64, 256>>>(hd, hd_stride, W + 4096, B + 64, fd, 64, nd);
    cudaMemsetAsync(denom, 0, (size_t)nd * sizeof(float));
    cudaMemsetAsync(agg, 0, (size_t)nd * 64 * sizeof(float));
    edge_fused<<<(E + 7) / 8, 256>>>(src, dst, fs, fd, attn, denom, agg, E);
    finish_kernel<<<(nd * 64 + 255) / 256, 256>>>(agg, denom, bias, resid, rstride, out, ostride, nd);
}

extern "C" void kernel_launch(void* const* d_in, const int* in_sizes, int n_in,
                              void* d_out, int out_size) {
    // Locate anchors in in_sizes (robust to either metadata ordering).
    int wf = -1, gf = -1;
    for (int i = 0; i < n_in; i++) {
        if (wf < 0 && in_sizes[i] == NUx * EMB) wf = i;   // eu
        if (gf < 0 && in_sizes[i] == ERx) gf = i;         // rate_src
    }
    if (wf < 0) wf = 0;
    if (gf < 0) gf = (wf == 0) ? 18 : 0;
    const float* eu        = (const float*)d_in[wf + 0];
    const float* ei        = (const float*)d_in[wf + 1];
    const float* rate_W    = (const float*)d_in[wf + 2];
    const float* rate_b    = (const float*)d_in[wf + 3];
    const float* rate_attn = (const float*)d_in[wf + 4];
    const float* rate_bias = (const float*)d_in[wf + 5];
    const float* rb_W      = (const float*)d_in[wf + 6];
    const float* rb_b      = (const float*)d_in[wf + 7];
    const float* rb_attn   = (const float*)d_in[wf + 8];
    const float* rb_bias   = (const float*)d_in[wf + 9];
    const float* tr_W      = (const float*)d_in[wf + 10];
    const float* tr_b      = (const float*)d_in[wf + 11];
    const float* tr_attn   = (const float*)d_in[wf + 12];
    const float* tr_bias   = (const float*)d_in[wf + 13];
    const float* attW1     = (const float*)d_in[wf + 14];
    const float* attb1     = (const float*)d_in[wf + 15];
    const float* attW2     = (const float*)d_in[wf + 16];
    const float* attb2     = (const float*)d_in[wf + 17];
    const int* rate_src  = (const int*)d_in[gf + 0];
    const int* rate_dst  = (const int*)d_in[gf + 1];
    const int* trust_src = (const int*)d_in[gf + 2];
    const int* trust_dst = (const int*)d_in[gf + 3];
    const int* pos_u     = (const int*)d_in[gf + 4];
    const int* pos_i     = (const int*)d_in[gf + 5];
    const int* neg_u     = (const int*)d_in[gf + 6];
    const int* neg_i     = (const int*)d_in[gf + 7];

    float* hu_all = sym_addr(g_hu_all);
    float* hi_all = sym_addr(g_hi_all);
    float* fs     = sym_addr(g_fs);
    float* fd     = sym_addr(g_fd);
    float* agg    = sym_addr(g_agg);
    float* denom  = sym_addr(g_denom);
    float* pbuf   = sym_addr(g_p);
    float* qbuf   = sym_addr(g_q);
    float* zinf   = sym_addr(g_zinf);
    float* zint   = sym_addr(g_zint);
    float* gate   = sym_addr(g_gate);
    float* sums   = sym_addr(g_sums);
    float* out    = (float*)d_out;

    // hu_all[:,0:64] = eu ; hi_all[:,0:64] = ei
    copy_block<<<(NUx * 64 + 255) / 256, 256>>>(eu, hu_all, HALL, NUx * 64);
    copy_block<<<(NIx * 64 + 255) / 256, 256>>>(ei, hi_all, HALL, NIx * 64);

    for (int l = 0; l < NLAYERS; l++) {
        const float* HU = hu_all + l * 64;        // stride HALL
        float* HUo      = hu_all + (l + 1) * 64;
        const float* HI = hi_all + l * 64;
        float* HIo      = hi_all + (l + 1) * 64;

        // rate: user -> item, residual + bias, write to HIo
        run_gat(HU, HALL, NUx, HI, HALL, NIx, rate_src, rate_dst, ERx,
                rate_W + (size_t)l * 2 * 4096, rate_b + (size_t)l * 2 * 64,
                rate_attn + l * 64, rate_bias + l * 64,
                HI, HALL, HIo, HALL, fs, fd, agg, denom);

        // rated-by: item -> user (reversed edges), write q
        run_gat(HI, HALL, NIx, HU, HALL, NUx, rate_dst, rate_src, ERx,
                rb_W + (size_t)l * 2 * 4096, rb_b + (size_t)l * 2 * 64,
                rb_attn + l * 64, rb_bias + l * 64,
                nullptr, 0, qbuf, 64, fs, fd, agg, denom);

        // trust: user -> user, write p
        run_gat(HU, HALL, NUx, HU, HALL, NUx, trust_src, trust_dst, ETx,
                tr_W + (size_t)l * 2 * 4096, tr_b + (size_t)l * 2 * 64,
                tr_attn + l * 64, tr_bias + l * 64,
                nullptr, 0, pbuf, 64, fs, fd, agg, denom);

        // gates
        gate_prep<<<1, 256>>>(attW1 + (size_t)l * 2 * 128 * 128,
                              attb1 + (size_t)l * 2 * 128,
                              attW2 + (size_t)l * 2 * 128,
                              attb2 + (size_t)l * 2, gate);
        cudaMemsetAsync(sums, 0, 4 * sizeof(float));
        z_kernel<<<(NUx + 7) / 8, 256>>>(HU, pbuf, qbuf, gate, zinf, zint, sums, NUx);
        gate_apply<<<(NUx + 7) / 8, 256>>>(HU, HUo, pbuf, qbuf, zinf, zint, sums, NUx);
    }

    pair_kernel<<<(EPx + 7) / 8, 256>>>(pos_u, pos_i, hu_all, hi_all, out, EPx);
    pair_kernel<<<(EPx + 7) / 8, 256>>>(neg_u, neg_i, hu_all, hi_all, out + EPx, EPx);
}

// round 4
// speedup vs baseline: 1.8548x; 1.2819x over previous
#include <cuda_runtime.h>
#include <math.h>

#define EMB 64
#define NLAYERS 2
#define NUx 100000
#define NIx 50000
#define ERx 1000000
#define ETx 800000
#define EPx 200000
#define HALL 192   // EMB*(1+L)

// ---------------- static scratch (no allocations allowed) ----------------
__device__ float g_hu_all[(size_t)NUx * HALL];
__device__ float g_hi_all[(size_t)NIx * HALL];
__device__ float g_fs[(size_t)NUx * EMB];
__device__ float g_fd[(size_t)NUx * EMB];
__device__ float g_p[(size_t)NUx * EMB];
__device__ float g_q[(size_t)NUx * EMB];
__device__ float g_zinf[NUx];
__device__ float g_zint[NUx];
__device__ float g_gate[264];   // [2][132]: v[128], c at 128
__device__ float g_sums[4];     // s_inf, ss_inf, s_int, ss_int
// CSR structures (edge lists are layer-invariant -> build once per call)
__device__ int g_deg[NUx];
__device__ int g_cursor[NUx];
__device__ int g_off_item[NIx + 1];
__device__ int g_off_urate[NUx + 1];
__device__ int g_off_trust[NUx + 1];
__device__ int g_val_item[ERx];    // src users grouped by dst item
__device__ int g_val_urate[ERx];   // dst items grouped by src user
__device__ int g_val_trust[ETx];   // src users grouped by dst user

// ---------------- kernels ----------------

__global__ void copy_block(const float* __restrict__ src, float* __restrict__ dst,
                           int dstride, int n64) {
    int i = blockIdx.x * blockDim.x + threadIdx.x;
    if (i >= n64) return;
    int row = i >> 6, j = i & 63;
    dst[(size_t)row * dstride + j] = src[i];
}

// ---- CSR build ----
__global__ void count_kernel(const int* __restrict__ grp, int* __restrict__ deg, int E) {
    int e = blockIdx.x * blockDim.x + threadIdx.x;
    if (e < E) atomicAdd(deg + grp[e], 1);
}

// single block, 1024 threads: exclusive scan of deg[0..n) into off[0..n]
__global__ void scan_kernel(const int* __restrict__ deg, int* __restrict__ off, int n) {
    __shared__ int ssum[1024];
    int t = threadIdx.x;
    int C = (n + 1023) >> 10;
    int base = t * C;
    int s = 0;
    for (int i = 0; i < C; i++) {
        int idx = base + i;
        if (idx < n) s += deg[idx];
    }
    ssum[t] = s;
    __syncthreads();
    for (int st = 1; st < 1024; st <<= 1) {
        int v = (t >= st) ? ssum[t - st] : 0;
        __syncthreads();
        ssum[t] += v;
        __syncthreads();
    }
    int run = (t == 0) ? 0 : ssum[t - 1];
    for (int i = 0; i < C; i++) {
        int idx = base + i;
        if (idx < n) { off[idx] = run; run += deg[idx]; }
    }
    if (t == 1023) off[n] = ssum[1023];
}

__global__ void scatter_kernel(const int* __restrict__ grp, const int* __restrict__ other,
                               int E, const int* __restrict__ off,
                               int* __restrict__ cursor, int* __restrict__ val) {
    int e = blockIdx.x * blockDim.x + threadIdx.x;
    if (e >= E) return;
    int d = grp[e];
    int pos = off[d] + atomicAdd(cursor + d, 1);
    val[pos] = other[e];
}

// ---- GEMM: Y[row,0:64] = X[row,0:64] @ W + B, using packed fma.rn.f32x2 ----
__global__ void gemm64v3(const float* __restrict__ X, int xstride,
                         const float* __restrict__ W, const float* __restrict__ Bv,
                         float* __restrict__ Y, int ystride, int n) {
    __shared__ float sW[64 * 64];       // sW[k*64 + c]
    __shared__ float sXT[64 * 68];      // sXT[k*68 + r]
    int tx = threadIdx.x;
    int row0 = blockIdx.x * 64;

    for (int i = tx; i < 1024; i += 256)
        ((float4*)sW)[i] = ((const float4*)W)[i];

    {
        int r = tx & 63, qu = tx >> 6;
        int row = row0 + r;
        if (row < n) {
            const float4* xr = (const float4*)(X + (size_t)row * xstride);
#pragma unroll
            for (int j = 0; j < 4; j++) {
                float4 v = xr[qu * 4 + j];
                int k = qu * 16 + j * 4;
                sXT[(k + 0) * 68 + r] = v.x;
                sXT[(k + 1) * 68 + r] = v.y;
                sXT[(k + 2) * 68 + r] = v.z;
                sXT[(k + 3) * 68 + r] = v.w;
            }
        } else {
#pragma unroll
            for (int j = 0; j < 4; j++) {
                int k = qu * 16 + j * 4;
                sXT[(k + 0) * 68 + r] = 0.f;
                sXT[(k + 1) * 68 + r] = 0.f;
                sXT[(k + 2) * 68 + r] = 0.f;
                sXT[(k + 3) * 68 + r] = 0.f;
            }
        }
    }
    __syncthreads();

    int ty = tx >> 4;    // rows 4ty..4ty+3
    int c  = tx & 15;    // cols 4c..4c+3
    float4 b0 = *(const float4*)(Bv + 4 * c);
    unsigned long long blo, bhi;
    asm("mov.b64 %0, {%1,%2};" : "=l"(blo) : "f"(b0.x), "f"(b0.y));
    asm("mov.b64 %0, {%1,%2};" : "=l"(bhi) : "f"(b0.z), "f"(b0.w));
    unsigned long long acc[4][2];
#pragma unroll
    for (int r = 0; r < 4; r++) { acc[r][0] = blo; acc[r][1] = bhi; }

#pragma unroll
    for (int k = 0; k < 64; k++) {
        ulonglong2 wv = ((const ulonglong2*)sW)[k * 16 + c];   // 4 floats as 2 packs
        float4 a4 = *(const float4*)(sXT + k * 68 + 4 * ty);
        unsigned long long pa0, pa1, pa2, pa3;
        asm("mov.b64 %0, {%1,%1};" : "=l"(pa0) : "f"(a4.x));
        asm("mov.b64 %0, {%1,%1};" : "=l"(pa1) : "f"(a4.y));
        asm("mov.b64 %0, {%1,%1};" : "=l"(pa2) : "f"(a4.z));
        asm("mov.b64 %0, {%1,%1};" : "=l"(pa3) : "f"(a4.w));
        asm("fma.rn.f32x2 %0, %1, %2, %0;" : "+l"(acc[0][0]) : "l"(pa0), "l"(wv.x));
        asm("fma.rn.f32x2 %0, %1, %2, %0;" : "+l"(acc[0][1]) : "l"(pa0), "l"(wv.y));
        asm("fma.rn.f32x2 %0, %1, %2, %0;" : "+l"(acc[1][0]) : "l"(pa1), "l"(wv.x));
        asm("fma.rn.f32x2 %0, %1, %2, %0;" : "+l"(acc[1][1]) : "l"(pa1), "l"(wv.y));
        asm("fma.rn.f32x2 %0, %1, %2, %0;" : "+l"(acc[2][0]) : "l"(pa2), "l"(wv.x));
        asm("fma.rn.f32x2 %0, %1, %2, %0;" : "+l"(acc[2][1]) : "l"(pa2), "l"(wv.y));
        asm("fma.rn.f32x2 %0, %1, %2, %0;" : "+l"(acc[3][0]) : "l"(pa3), "l"(wv.x));
        asm("fma.rn.f32x2 %0, %1, %2, %0;" : "+l"(acc[3][1]) : "l"(pa3), "l"(wv.y));
    }
    int rbase = row0 + 4 * ty;
#pragma unroll
    for (int r = 0; r < 4; r++) {
        if (rbase + r < n) {
            ulonglong2 o = make_ulonglong2(acc[r][0], acc[r][1]);
            *(ulonglong2*)(Y + (size_t)(rbase + r) * ystride + 4 * c) = o;
        }
    }
}

// ---- GAT gather: one warp per dst node, no atomics, finish fused ----
__global__ void gat_gather(const int* __restrict__ off, const int* __restrict__ val,
                           const float* __restrict__ fs, const float* __restrict__ fd,
                           const float* __restrict__ attn, const float* __restrict__ bias,
                           const float* __restrict__ resid, int rstride,
                           float* __restrict__ out, int ostride, int n) {
    int node = (blockIdx.x * blockDim.x + threadIdx.x) >> 5;
    int lane = threadIdx.x & 31;
    if (node >= n) return;
    float2 fdv = ((const float2*)(fd + (size_t)node * 64))[lane];
    float2 at  = ((const float2*)attn)[lane];
    int b = off[node], e = off[node + 1];
    float denom = 0.f;
    float2 acc = make_float2(0.f, 0.f);

    float2 a_next = make_float2(0.f, 0.f);
    if (b < e) {
        int s0 = val[b];
        a_next = ((const float2*)(fs + (size_t)s0 * 64))[lane];
    }
    for (int j = b; j < e; j++) {
        float2 a = a_next;
        int jn = j + 1;
        if (jn < e) {
            int sn = val[jn];
            a_next = ((const float2*)(fs + (size_t)sn * 64))[lane];
        }
        float x0 = a.x + fdv.x, x1 = a.y + fdv.y;
        x0 = x0 > 0.f ? x0 : 0.2f * x0;
        x1 = x1 > 0.f ? x1 : 0.2f * x1;
        float p = x0 * at.x + x1 * at.y;
#pragma unroll
        for (int o = 16; o; o >>= 1) p += __shfl_xor_sync(0xffffffffu, p, o);
        float ex = __expf(p);
        denom += ex;
        acc.x += ex * a.x;
        acc.y += ex * a.y;
    }
    float inv = denom > 0.f ? 1.0f / denom : 0.f;
    float2 bv = ((const float2*)bias)[lane];
    float2 o2;
    o2.x = acc.x * inv + bv.x;
    o2.y = acc.y * inv + bv.y;
    if (resid) {
        float2 rv = ((const float2*)(resid + (size_t)node * rstride))[lane];
        o2.x += rv.x; o2.y += rv.y;
    }
    ((float2*)(out + (size_t)node * ostride))[lane] = o2;
}

// collapse gate MLP: v[k] = sum_j W1[k][j]*W2[j];  c = b1.W2 + b2
__global__ void gate_prep(const float* __restrict__ W1, const float* __restrict__ b1,
                          const float* __restrict__ W2, const float* __restrict__ b2,
                          float* __restrict__ gout) {
    int t = threadIdx.x;          // 256
    int i = t >> 7, k = t & 127;
    const float* w1 = W1 + (size_t)i * 128 * 128 + (size_t)k * 128;
    const float* w2 = W2 + i * 128;
    float v = 0.f;
    for (int j = 0; j < 128; j++) v += w1[j] * w2[j];
    gout[i * 132 + k] = v;
    if (k == 0) {
        float c = b2[i];
        const float* bb = b1 + i * 128;
        for (int j = 0; j < 128; j++) c += bb[j] * w2[j];
        gout[i * 132 + 128] = c;
    }
}

// z_inf = [hu,p].v_inf + c ; z_int = [hu,q].v_int + c ; accumulate BN stats
__global__ void z_kernel(const float* __restrict__ HU, const float* __restrict__ p,
                         const float* __restrict__ q, const float* __restrict__ gate,
                         float* __restrict__ zinf, float* __restrict__ zint,
                         float* __restrict__ sums, int n) {
    __shared__ float red[8][4];
    int w = (blockIdx.x * blockDim.x + threadIdx.x) >> 5;
    int wl = threadIdx.x >> 5;
    int lane = threadIdx.x & 31;
    float zi = 0.f, zt = 0.f;
    if (w < n) {
        float2 h  = ((const float2*)(HU + (size_t)w * HALL))[lane];
        float2 pv = ((const float2*)(p  + (size_t)w * 64))[lane];
        float2 qv = ((const float2*)(q  + (size_t)w * 64))[lane];
        const float2* vinf = (const float2*)gate;
        const float2* vint = (const float2*)(gate + 132);
        float2 vi0 = vinf[lane], vi1 = vinf[32 + lane];
        float2 vt0 = vint[lane], vt1 = vint[32 + lane];
        zi = h.x * vi0.x + h.y * vi0.y + pv.x * vi1.x + pv.y * vi1.y;
        zt = h.x * vt0.x + h.y * vt0.y + qv.x * vt1.x + qv.y * vt1.y;
    }
#pragma unroll
    for (int off = 16; off; off >>= 1) {
        zi += __shfl_down_sync(0xffffffffu, zi, off);
        zt += __shfl_down_sync(0xffffffffu, zt, off);
    }
    if (lane == 0) {
        if (w < n) {
            zi += gate[128]; zt += gate[132 + 128];
            zinf[w] = zi; zint[w] = zt;
            red[wl][0] = zi; red[wl][1] = zi * zi;
            red[wl][2] = zt; red[wl][3] = zt * zt;
        } else {
            red[wl][0] = red[wl][1] = red[wl][2] = red[wl][3] = 0.f;
        }
    }
    __syncthreads();
    if (threadIdx.x < 4) {
        float s = 0.f;
        for (int k = 0; k < 8; k++) s += red[k][threadIdx.x];
        atomicAdd(sums + threadIdx.x, s);
    }
}

// BN + leaky(0.01) + softmax gate; HUo = g0*p + g1*q + HU
__global__ void gate_apply(const float* __restrict__ HU, float* __restrict__ HUo,
                           const float* __restrict__ p, const float* __restrict__ q,
                           const float* __restrict__ zinf, const float* __restrict__ zint,
                           const float* __restrict__ sums, int n) {
    int w = (blockIdx.x * blockDim.x + threadIdx.x) >> 5;
    int lane = threadIdx.x & 31;
    if (w >= n) return;
    float inv = 1.0f / (float)n;
    float mu0 = sums[0] * inv;
    float var0 = sums[1] * inv - mu0 * mu0;
    float mu1 = sums[2] * inv;
    float var1 = sums[3] * inv - mu1 * mu1;
    float a0 = (zinf[w] - mu0) * rsqrtf(var0 + 1e-5f);
    float a1 = (zint[w] - mu1) * rsqrtf(var1 + 1e-5f);
    a0 = a0 > 0.f ? a0 : 0.01f * a0;
    a1 = a1 > 0.f ? a1 : 0.01f * a1;
    float m = fmaxf(a0, a1);
    float e0 = __expf(a0 - m), e1 = __expf(a1 - m);
    float g0 = e0 / (e0 + e1), g1 = e1 / (e0 + e1);
    float2 pv = ((const float2*)(p + (size_t)w * 64))[lane];
    float2 qv = ((const float2*)(q + (size_t)w * 64))[lane];
    float2 hv = ((const float2*)(HU + (size_t)w * HALL))[lane];
    float2 o;
    o.x = g0 * pv.x + g1 * qv.x + hv.x;
    o.y = g0 * pv.y + g1 * qv.y + hv.y;
    ((float2*)(HUo + (size_t)w * HALL))[lane] = o;
}

__global__ void pair_kernel(const int* __restrict__ uu, const int* __restrict__ ii,
                            const float* __restrict__ hu_all, const float* __restrict__ hi_all,
                            float* __restrict__ out, int np) {
    int w = (blockIdx.x * blockDim.x + threadIdx.x) >> 5;
    int lane = threadIdx.x & 31;
    if (w >= np) return;
    const float* hr = hu_all + (size_t)uu[w] * HALL;
    const float* ir = hi_all + (size_t)ii[w] * HALL;
    float s = 0.f;
#pragma unroll
    for (int c = 0; c < 6; c++) s += hr[lane + 32 * c] * ir[lane + 32 * c];
#pragma unroll
    for (int off = 16; off; off >>= 1) s += __shfl_down_sync(0xffffffffu, s, off);
    if (lane == 0) out[w] = s;
}

// ---------------- host ----------------

static float* sym_addr(const void* s) {
    void* p = nullptr;
    cudaGetSymbolAddress(&p, s);
    return (float*)p;
}

static void build_csr(const int* grp, const int* other, int E, int n,
                      int* off, int* val, int* deg, int* cursor) {
    cudaMemsetAsync(deg, 0, (size_t)n * sizeof(int));
    count_kernel<<<(E + 255) / 256, 256>>>(grp, deg, E);
    scan_kernel<<<1, 1024>>>(deg, off, n);
    cudaMemsetAsync(cursor, 0, (size_t)n * sizeof(int));
    scatter_kernel<<<(E + 255) / 256, 256>>>(grp, other, E, off, cursor, val);
}

static void run_gat(const float* hs, int hs_stride, int ns,
                    const float* hd, int hd_stride, int nd,
                    const int* off, const int* val,
                    const float* W, const float* B, const float* attn, const float* bias,
                    const float* resid, int rstride, float* out, int ostride,
                    float* fs, float* fd) {
    gemm64v3<<<(ns + 63) / 64, 256>>>(hs, hs_stride, W, B, fs, 64, ns);
    gemm64v3<<<(nd + 63) / 64, 256>>>(hd, hd_stride, W + 4096, B + 64, fd, 64, nd);
    gat_gather<<<(nd * 32 + 255) / 256, 256>>>(off, val, fs, fd, attn, bias,
                                               resid, rstride, out, ostride, nd);
}

extern "C" void kernel_launch(void* const* d_in, const int* in_sizes, int n_in,
                              void* d_out, int out_size) {
    int wf = -1, gf = -1;
    for (int i = 0; i < n_in; i++) {
        if (wf < 0 && in_sizes[i] == NUx * EMB) wf = i;   // eu
        if (gf < 0 && in_sizes[i] == ERx) gf = i;         // rate_src
    }
    if (wf < 0) wf = 0;
    if (gf < 0) gf = (wf == 0) ? 18 : 0;
    const float* eu        = (const float*)d_in[wf + 0];
    const float* ei        = (const float*)d_in[wf + 1];
    const float* rate_W    = (const float*)d_in[wf + 2];
    const float* rate_b    = (const float*)d_in[wf + 3];
    const float* rate_attn = (const float*)d_in[wf + 4];
    const float* rate_bias = (const float*)d_in[wf + 5];
    const float* rb_W      = (const float*)d_in[wf + 6];
    const float* rb_b      = (const float*)d_in[wf + 7];
    const float* rb_attn   = (const float*)d_in[wf + 8];
    const float* rb_bias   = (const float*)d_in[wf + 9];
    const float* tr_W      = (const float*)d_in[wf + 10];
    const float* tr_b      = (const float*)d_in[wf + 11];
    const float* tr_attn   = (const float*)d_in[wf + 12];
    const float* tr_bias   = (const float*)d_in[wf + 13];
    const float* attW1     = (const float*)d_in[wf + 14];
    const float* attb1     = (const float*)d_in[wf + 15];
    const float* attW2     = (const float*)d_in[wf + 16];
    const float* attb2     = (const float*)d_in[wf + 17];
    const int* rate_src  = (const int*)d_in[gf + 0];
    const int* rate_dst  = (const int*)d_in[gf + 1];
    const int* trust_src = (const int*)d_in[gf + 2];
    const int* trust_dst = (const int*)d_in[gf + 3];
    const int* pos_u     = (const int*)d_in[gf + 4];
    const int* pos_i     = (const int*)d_in[gf + 5];
    const int* neg_u     = (const int*)d_in[gf + 6];
    const int* neg_i     = (const int*)d_in[gf + 7];

    float* hu_all = sym_addr(g_hu_all);
    float* hi_all = sym_addr(g_hi_all);
    float* fs     = sym_addr(g_fs);
    float* fd     = sym_addr(g_fd);
    float* pbuf   = sym_addr(g_p);
    float* qbuf   = sym_addr(g_q);
    float* zinf   = sym_addr(g_zinf);
    float* zint   = sym_addr(g_zint);
    float* gate   = sym_addr(g_gate);
    float* sums   = sym_addr(g_sums);
    int* deg      = (int*)sym_addr(g_deg);
    int* cursor   = (int*)sym_addr(g_cursor);
    int* off_item  = (int*)sym_addr(g_off_item);
    int* off_urate = (int*)sym_addr(g_off_urate);
    int* off_trust = (int*)sym_addr(g_off_trust);
    int* val_item  = (int*)sym_addr(g_val_item);
    int* val_urate = (int*)sym_addr(g_val_urate);
    int* val_trust = (int*)sym_addr(g_val_trust);
    float* out    = (float*)d_out;

    // Build CSRs (layer-invariant)
    build_csr(rate_dst,  rate_src,  ERx, NIx, off_item,  val_item,  deg, cursor);
    build_csr(rate_src,  rate_dst,  ERx, NUx, off_urate, val_urate, deg, cursor);
    build_csr(trust_dst, trust_src, ETx, NUx, off_trust, val_trust, deg, cursor);

    // hu_all[:,0:64] = eu ; hi_all[:,0:64] = ei
    copy_block<<<(NUx * 64 + 255) / 256, 256>>>(eu, hu_all, HALL, NUx * 64);
    copy_block<<<(NIx * 64 + 255) / 256, 256>>>(ei, hi_all, HALL, NIx * 64);

    for (int l = 0; l < NLAYERS; l++) {
        const float* HU = hu_all + l * 64;        // stride HALL
        float* HUo      = hu_all + (l + 1) * 64;
        const float* HI = hi_all + l * 64;
        float* HIo      = hi_all + (l + 1) * 64;

        // rate: user -> item, residual + bias, write to HIo
        run_gat(HU, HALL, NUx, HI, HALL, NIx, off_item, val_item,
                rate_W + (size_t)l * 2 * 4096, rate_b + (size_t)l * 2 * 64,
                rate_attn + l * 64, rate_bias + l * 64,
                HI, HALL, HIo, HALL, fs, fd);

        // rated-by: item -> user (reversed edges), write q
        run_gat(HI, HALL, NIx, HU, HALL, NUx, off_urate, val_urate,
                rb_W + (size_t)l * 2 * 4096, rb_b + (size_t)l * 2 * 64,
                rb_attn + l * 64, rb_bias + l * 64,
                nullptr, 0, qbuf, 64, fs, fd);

        // trust: user -> user, write p
        run_gat(HU, HALL, NUx, HU, HALL, NUx, off_trust, val_trust,
                tr_W + (size_t)l * 2 * 4096, tr_b + (size_t)l * 2 * 64,
                tr_attn + l * 64, tr_bias + l * 64,
                nullptr, 0, pbuf, 64, fs, fd);

        // gates
        gate_prep<<<1, 256>>>(attW1 + (size_t)l * 2 * 128 * 128,
                              attb1 + (size_t)l * 2 * 128,
                              attW2 + (size_t)l * 2 * 128,
                              attb2 + (size_t)l * 2, gate);
        cudaMemsetAsync(sums, 0, 4 * sizeof(float));
        z_kernel<<<(NUx + 7) / 8, 256>>>(HU, pbuf, qbuf, gate, zinf, zint, sums, NUx);
        gate_apply<<<(NUx + 7) / 8, 256>>>(HU, HUo, pbuf, qbuf, zinf, zint, sums, NUx);
    }

    pair_kernel<<<(EPx + 7) / 8, 256>>>(pos_u, pos_i, hu_all, hi_all, out, EPx);
    pair_kernel<<<(EPx + 7) / 8, 256>>>(neg_u, neg_i, hu_all, hi_all, out + EPx, EPx);
}

// round 5
// speedup vs baseline: 2.1127x; 1.1390x over previous
#include <cuda_runtime.h>
#include <math.h>

#define EMB 64
#define NLAYERS 2
#define NUx 100000
#define NIx 50000
#define ERx 1000000
#define ETx 800000
#define EPx 200000
#define HALL 192   // EMB*(1+L)

// ---------------- static scratch (no allocations allowed) ----------------
__device__ float g_hu_all[(size_t)NUx * HALL];
__device__ float g_hi_all[(size_t)NIx * HALL];
// per-relation projected features (all live simultaneously now)
__device__ float g_fsU_rate[(size_t)NUx * EMB];
__device__ float g_fdU_rb[(size_t)NUx * EMB];
__device__ float g_fsU_tr[(size_t)NUx * EMB];
__device__ float g_fdU_tr[(size_t)NUx * EMB];
__device__ float g_fdI_rate[(size_t)NIx * EMB];
__device__ float g_fsI_rb[(size_t)NIx * EMB];
__device__ float g_p[(size_t)NUx * EMB];
__device__ float g_q[(size_t)NUx * EMB];
__device__ float g_zinf[NUx];
__device__ float g_zint[NUx];
__device__ float g_gate[264];   // [2][132]: v[128], c at 128
__device__ float g_sums[4];
// CSR structures (edge lists are layer-invariant -> build once per call)
__device__ int g_deg[NUx];
__device__ int g_cursor[NUx];
__device__ int g_bsum[64];
__device__ int g_off_item[NIx + 1];
__device__ int g_off_urate[NUx + 1];
__device__ int g_off_trust[NUx + 1];
__device__ int g_val_item[ERx];
__device__ int g_val_urate[ERx];
__device__ int g_val_trust[ETx];

// ---------------- job descriptors ----------------
struct GJob { const float* W; const float* B; float* Y; };
struct GJobs { GJob j[4]; int m; };

struct GatJob {
    const int* off; const int* val; const float* fs; const float* fd;
    const float* attn; const float* bias; const float* resid; int rstride;
    float* out; int ostride; int n;
};
struct GatJobs { GatJob j[3]; int n0, n01, ntot; };

// ---------------- kernels ----------------

__global__ void copy_block(const float* __restrict__ src, float* __restrict__ dst,
                           int dstride, int n64) {
    int i = blockIdx.x * blockDim.x + threadIdx.x;
    if (i >= n64) return;
    int row = i >> 6, j = i & 63;
    dst[(size_t)row * dstride + j] = src[i];
}

// ---- CSR build ----
__global__ void count_kernel(const int* __restrict__ grp, int* __restrict__ deg, int E) {
    int e = blockIdx.x * blockDim.x + threadIdx.x;
    if (e < E) atomicAdd(deg + grp[e], 1);
}

// per-block (4096-chunk) totals
__global__ void scan_bsums(const int* __restrict__ deg, int n, int* __restrict__ bsum) {
    __shared__ int sh[256];
    int t = threadIdx.x;
    int base = blockIdx.x * 4096;
    int s = 0;
#pragma unroll
    for (int i = 0; i < 16; i++) {
        int idx = base + i * 256 + t;
        if (idx < n) s += deg[idx];
    }
    sh[t] = s;
    __syncthreads();
    for (int st = 128; st; st >>= 1) {
        if (t < st) sh[t] += sh[t + st];
        __syncthreads();
    }
    if (t == 0) bsum[blockIdx.x] = sh[0];
}

// single block: exclusive scan of bsum[0..nb), write grand total to *total
__global__ void scan_tops(int* __restrict__ bsum, int nb, int* __restrict__ total) {
    __shared__ int sh[64];
    int t = threadIdx.x;   // 64 threads
    int v = (t < nb) ? bsum[t] : 0;
    sh[t] = v;
    __syncthreads();
    for (int st = 1; st < 64; st <<= 1) {
        int x = (t >= st) ? sh[t - st] : 0;
        __syncthreads();
        sh[t] += x;
        __syncthreads();
    }
    if (t < nb) bsum[t] = sh[t] - v;     // exclusive
    if (t == 63) *total = sh[63];
}

__global__ void scan_final(const int* __restrict__ deg, int n,
                           const int* __restrict__ bsum, int* __restrict__ off) {
    __shared__ int sh[256];
    int t = threadIdx.x;
    int base = blockIdx.x * 4096 + t * 16;
    int local[16];
    int s = 0;
#pragma unroll
    for (int i = 0; i < 16; i++) {
        int idx = base + i;
        int d = (idx < n) ? deg[idx] : 0;
        local[i] = d;
        s += d;
    }
    sh[t] = s;
    __syncthreads();
    int v = s;
    for (int st = 1; st < 256; st <<= 1) {
        int x = (t >= st) ? sh[t - st] : 0;
        __syncthreads();
        sh[t] += x;
        __syncthreads();
    }
    int run = bsum[blockIdx.x] + sh[t] - v;
#pragma unroll
    for (int i = 0; i < 16; i++) {
        int idx = base + i;
        if (idx < n) off[idx] = run;
        run += local[i];
    }
}

__global__ void scatter_kernel(const int* __restrict__ grp, const int* __restrict__ other,
                               int E, const int* __restrict__ off,
                               int* __restrict__ cursor, int* __restrict__ val) {
    int e = blockIdx.x * blockDim.x + threadIdx.x;
    if (e >= E) return;
    int d = grp[e];
    int pos = off[d] + atomicAdd(cursor + d, 1);
    val[pos] = other[e];
}

// ---- batched GEMM: for each job, Y[row,0:64] = X[row,0:64] @ W + B ----
// X tile transposed to shared once; W double-buffered; FFMA2 inner loop.
__global__ void gemm64_multi(const float* __restrict__ X, int xstride, int n, GJobs jobs) {
    __shared__ float sW[2][4096];
    __shared__ float sXT[64 * 68];
    int tx = threadIdx.x;
    int row0 = blockIdx.x * 64;

    // transpose X tile into sXT
    {
        int r = tx & 63, qu = tx >> 6;
        int row = row0 + r;
        if (row < n) {
            const float4* xr = (const float4*)(X + (size_t)row * xstride);
#pragma unroll
            for (int j = 0; j < 4; j++) {
                float4 v = xr[qu * 4 + j];
                int k = qu * 16 + j * 4;
                sXT[(k + 0) * 68 + r] = v.x;
                sXT[(k + 1) * 68 + r] = v.y;
                sXT[(k + 2) * 68 + r] = v.z;
                sXT[(k + 3) * 68 + r] = v.w;
            }
        } else {
#pragma unroll
            for (int j = 0; j < 4; j++) {
                int k = qu * 16 + j * 4;
                sXT[(k + 0) * 68 + r] = 0.f;
                sXT[(k + 1) * 68 + r] = 0.f;
                sXT[(k + 2) * 68 + r] = 0.f;
                sXT[(k + 3) * 68 + r] = 0.f;
            }
        }
    }
    // preload W of job 0
    for (int i = tx; i < 1024; i += 256)
        ((float4*)sW[0])[i] = ((const float4*)jobs.j[0].W)[i];
    __syncthreads();

    int ty = tx >> 4;    // rows 4ty..4ty+3
    int c  = tx & 15;    // cols 4c..4c+3
    int rbase = row0 + 4 * ty;

    for (int m = 0; m < jobs.m; m++) {
        const float* Bm; float* Ym;
        const float* Wnext = nullptr;
        switch (m) {
            case 0: Bm = jobs.j[0].B; Ym = jobs.j[0].Y; break;
            case 1: Bm = jobs.j[1].B; Ym = jobs.j[1].Y; break;
            case 2: Bm = jobs.j[2].B; Ym = jobs.j[2].Y; break;
            default: Bm = jobs.j[3].B; Ym = jobs.j[3].Y; break;
        }
        if (m + 1 < jobs.m) {
            switch (m + 1) {
                case 1: Wnext = jobs.j[1].W; break;
                case 2: Wnext = jobs.j[2].W; break;
                default: Wnext = jobs.j[3].W; break;
            }
        }
        // prefetch next W into other buffer (safe: that buffer's readers synced last iter)
        if (Wnext) {
            float4* wd = (float4*)sW[(m + 1) & 1];
            const float4* ws = (const float4*)Wnext;
            for (int i = tx; i < 1024; i += 256) wd[i] = ws[i];
        }
        const float* Wcur = sW[m & 1];

        float4 b0 = *(const float4*)(Bm + 4 * c);
        unsigned long long blo, bhi;
        asm("mov.b64 %0, {%1,%2};" : "=l"(blo) : "f"(b0.x), "f"(b0.y));
        asm("mov.b64 %0, {%1,%2};" : "=l"(bhi) : "f"(b0.z), "f"(b0.w));
        unsigned long long acc[4][2];
#pragma unroll
        for (int r = 0; r < 4; r++) { acc[r][0] = blo; acc[r][1] = bhi; }

#pragma unroll
        for (int k = 0; k < 64; k++) {
            ulonglong2 wv = ((const ulonglong2*)Wcur)[k * 16 + c];
            float4 a4 = *(const float4*)(sXT + k * 68 + 4 * ty);
            unsigned long long pa0, pa1, pa2, pa3;
            asm("mov.b64 %0, {%1,%1};" : "=l"(pa0) : "f"(a4.x));
            asm("mov.b64 %0, {%1,%1};" : "=l"(pa1) : "f"(a4.y));
            asm("mov.b64 %0, {%1,%1};" : "=l"(pa2) : "f"(a4.z));
            asm("mov.b64 %0, {%1,%1};" : "=l"(pa3) : "f"(a4.w));
            asm("fma.rn.f32x2 %0, %1, %2, %0;" : "+l"(acc[0][0]) : "l"(pa0), "l"(wv.x));
            asm("fma.rn.f32x2 %0, %1, %2, %0;" : "+l"(acc[0][1]) : "l"(pa0), "l"(wv.y));
            asm("fma.rn.f32x2 %0, %1, %2, %0;" : "+l"(acc[1][0]) : "l"(pa1), "l"(wv.x));
            asm("fma.rn.f32x2 %0, %1, %2, %0;" : "+l"(acc[1][1]) : "l"(pa1), "l"(wv.y));
            asm("fma.rn.f32x2 %0, %1, %2, %0;" : "+l"(acc[2][0]) : "l"(pa2), "l"(wv.x));
            asm("fma.rn.f32x2 %0, %1, %2, %0;" : "+l"(acc[2][1]) : "l"(pa2), "l"(wv.y));
            asm("fma.rn.f32x2 %0, %1, %2, %0;" : "+l"(acc[3][0]) : "l"(pa3), "l"(wv.x));
            asm("fma.rn.f32x2 %0, %1, %2, %0;" : "+l"(acc[3][1]) : "l"(pa3), "l"(wv.y));
        }
#pragma unroll
        for (int r = 0; r < 4; r++) {
            if (rbase + r < n) {
                ulonglong2 o = make_ulonglong2(acc[r][0], acc[r][1]);
                *(ulonglong2*)(Ym + (size_t)(rbase + r) * 64 + 4 * c) = o;
            }
        }
        __syncthreads();
    }
}

// ---- merged GAT gather: one warp per dst node, 3 relations in one launch ----
__global__ void gat_gather3(GatJobs jobs) {
    int w = (blockIdx.x * blockDim.x + threadIdx.x) >> 5;
    int lane = threadIdx.x & 31;
    if (w >= jobs.ntot) return;
    GatJob jb;
    int node;
    if (w < jobs.n0)        { jb = jobs.j[0]; node = w; }
    else if (w < jobs.n01)  { jb = jobs.j[1]; node = w - jobs.n0; }
    else                    { jb = jobs.j[2]; node = w - jobs.n01; }

    float2 fdv = ((const float2*)(jb.fd + (size_t)node * 64))[lane];
    float2 at  = ((const float2*)jb.attn)[lane];
    int b = jb.off[node], e = jb.off[node + 1];
    float denom = 0.f;
    float2 acc = make_float2(0.f, 0.f);
    const float* fs = jb.fs;
    const int* val = jb.val;

    float2 nA0, nA1;
    if (b < e) {
        int s0 = val[b];
        int s1 = val[min(b + 1, e - 1)];
        nA0 = ((const float2*)(fs + (size_t)s0 * 64))[lane];
        nA1 = ((const float2*)(fs + (size_t)s1 * 64))[lane];
    }
    for (int j = b; j < e; j += 2) {
        float2 A0 = nA0, A1 = nA1;
        int jn = j + 2;
        if (jn < e) {
            int s0 = val[jn];
            int s1 = val[min(jn + 1, e - 1)];
            nA0 = ((const float2*)(fs + (size_t)s0 * 64))[lane];
            nA1 = ((const float2*)(fs + (size_t)s1 * 64))[lane];
        }
        float x0 = A0.x + fdv.x, x1 = A0.y + fdv.y;
        float y0 = A1.x + fdv.x, y1 = A1.y + fdv.y;
        x0 = x0 > 0.f ? x0 : 0.2f * x0;
        x1 = x1 > 0.f ? x1 : 0.2f * x1;
        y0 = y0 > 0.f ? y0 : 0.2f * y0;
        y1 = y1 > 0.f ? y1 : 0.2f * y1;
        float p0 = x0 * at.x + x1 * at.y;
        float p1 = y0 * at.x + y1 * at.y;
#pragma unroll
        for (int o = 16; o; o >>= 1) {
            p0 += __shfl_xor_sync(0xffffffffu, p0, o);
            p1 += __shfl_xor_sync(0xffffffffu, p1, o);
        }
        float ex0 = __expf(p0);
        denom += ex0;
        acc.x += ex0 * A0.x;
        acc.y += ex0 * A0.y;
        if (j + 1 < e) {
            float ex1 = __expf(p1);
            denom += ex1;
            acc.x += ex1 * A1.x;
            acc.y += ex1 * A1.y;
        }
    }
    float inv = denom > 0.f ? 1.0f / denom : 0.f;
    float2 bv = ((const float2*)jb.bias)[lane];
    float2 o2;
    o2.x = acc.x * inv + bv.x;
    o2.y = acc.y * inv + bv.y;
    if (jb.resid) {
        float2 rv = ((const float2*)(jb.resid + (size_t)node * jb.rstride))[lane];
        o2.x += rv.x; o2.y += rv.y;
    }
    ((float2*)(jb.out + (size_t)node * jb.ostride))[lane] = o2;
}

// collapse gate MLP: v[k] = sum_j W1[k][j]*W2[j];  c = b1.W2 + b2
__global__ void gate_prep(const float* __restrict__ W1, const float* __restrict__ b1,
                          const float* __restrict__ W2, const float* __restrict__ b2,
                          float* __restrict__ gout) {
    int t = threadIdx.x;          // 256
    int i = t >> 7, k = t & 127;
    const float* w1 = W1 + (size_t)i * 128 * 128 + (size_t)k * 128;
    const float* w2 = W2 + i * 128;
    float v = 0.f;
    for (int j = 0; j < 128; j++) v += w1[j] * w2[j];
    gout[i * 132 + k] = v;
    if (k == 0) {
        float c = b2[i];
        const float* bb = b1 + i * 128;
        for (int j = 0; j < 128; j++) c += bb[j] * w2[j];
        gout[i * 132 + 128] = c;
    }
}

__global__ void z_kernel(const float* __restrict__ HU, const float* __restrict__ p,
                         const float* __restrict__ q, const float* __restrict__ gate,
                         float* __restrict__ zinf, float* __restrict__ zint,
                         float* __restrict__ sums, int n) {
    __shared__ float red[8][4];
    int w = (blockIdx.x * blockDim.x + threadIdx.x) >> 5;
    int wl = threadIdx.x >> 5;
    int lane = threadIdx.x & 31;
    float zi = 0.f, zt = 0.f;
    if (w < n) {
        float2 h  = ((const float2*)(HU + (size_t)w * HALL))[lane];
        float2 pv = ((const float2*)(p  + (size_t)w * 64))[lane];
        float2 qv = ((const float2*)(q  + (size_t)w * 64))[lane];
        const float2* vinf = (const float2*)gate;
        const float2* vint = (const float2*)(gate + 132);
        float2 vi0 = vinf[lane], vi1 = vinf[32 + lane];
        float2 vt0 = vint[lane], vt1 = vint[32 + lane];
        zi = h.x * vi0.x + h.y * vi0.y + pv.x * vi1.x + pv.y * vi1.y;
        zt = h.x * vt0.x + h.y * vt0.y + qv.x * vt1.x + qv.y * vt1.y;
    }
#pragma unroll
    for (int off = 16; off; off >>= 1) {
        zi += __shfl_down_sync(0xffffffffu, zi, off);
        zt += __shfl_down_sync(0xffffffffu, zt, off);
    }
    if (lane == 0) {
        if (w < n) {
            zi += gate[128]; zt += gate[132 + 128];
            zinf[w] = zi; zint[w] = zt;
            red[wl][0] = zi; red[wl][1] = zi * zi;
            red[wl][2] = zt; red[wl][3] = zt * zt;
        } else {
            red[wl][0] = red[wl][1] = red[wl][2] = red[wl][3] = 0.f;
        }
    }
    __syncthreads();
    if (threadIdx.x < 4) {
        float s = 0.f;
        for (int k = 0; k < 8; k++) s += red[k][threadIdx.x];
        atomicAdd(sums + threadIdx.x, s);
    }
}

__global__ void gate_apply(const float* __restrict__ HU, float* __restrict__ HUo,
                           const float* __restrict__ p, const float* __restrict__ q,
                           const float* __restrict__ zinf, const float* __restrict__ zint,
                           const float* __restrict__ sums, int n) {
    int w = (blockIdx.x * blockDim.x + threadIdx.x) >> 5;
    int lane = threadIdx.x & 31;
    if (w >= n) return;
    float inv = 1.0f / (float)n;
    float mu0 = sums[0] * inv;
    float var0 = sums[1] * inv - mu0 * mu0;
    float mu1 = sums[2] * inv;
    float var1 = sums[3] * inv - mu1 * mu1;
    float a0 = (zinf[w] - mu0) * rsqrtf(var0 + 1e-5f);
    float a1 = (zint[w] - mu1) * rsqrtf(var1 + 1e-5f);
    a0 = a0 > 0.f ? a0 : 0.01f * a0;
    a1 = a1 > 0.f ? a1 : 0.01f * a1;
    float m = fmaxf(a0, a1);
    float e0 = __expf(a0 - m), e1 = __expf(a1 - m);
    float g0 = e0 / (e0 + e1), g1 = e1 / (e0 + e1);
    float2 pv = ((const float2*)(p + (size_t)w * 64))[lane];
    float2 qv = ((const float2*)(q + (size_t)w * 64))[lane];
    float2 hv = ((const float2*)(HU + (size_t)w * HALL))[lane];
    float2 o;
    o.x = g0 * pv.x + g1 * qv.x + hv.x;
    o.y = g0 * pv.y + g1 * qv.y + hv.y;
    ((float2*)(HUo + (size_t)w * HALL))[lane] = o;
}

__global__ void pair_kernel(const int* __restrict__ uu, const int* __restrict__ ii,
                            const float* __restrict__ hu_all, const float* __restrict__ hi_all,
                            float* __restrict__ out, int np) {
    int w = (blockIdx.x * blockDim.x + threadIdx.x) >> 5;
    int lane = threadIdx.x & 31;
    if (w >= np) return;
    const float* hr = hu_all + (size_t)uu[w] * HALL;
    const float* ir = hi_all + (size_t)ii[w] * HALL;
    float s = 0.f;
#pragma unroll
    for (int c = 0; c < 6; c++) s += hr[lane + 32 * c] * ir[lane + 32 * c];
#pragma unroll
    for (int off = 16; off; off >>= 1) s += __shfl_down_sync(0xffffffffu, s, off);
    if (lane == 0) out[w] = s;
}

// ---------------- host ----------------

static float* sym_addr(const void* s) {
    void* p = nullptr;
    cudaGetSymbolAddress(&p, s);
    return (float*)p;
}

static void build_csr(const int* grp, const int* other, int E, int n,
                      int* off, int* val, int* deg, int* cursor, int* bsum) {
    int nb = (n + 4095) / 4096;
    cudaMemsetAsync(deg, 0, (size_t)n * sizeof(int));
    count_kernel<<<(E + 255) / 256, 256>>>(grp, deg, E);
    scan_bsums<<<nb, 256>>>(deg, n, bsum);
    scan_tops<<<1, 64>>>(bsum, nb, off + n);
    scan_final<<<nb, 256>>>(deg, n, bsum, off);
    cudaMemsetAsync(cursor, 0, (size_t)n * sizeof(int));
    scatter_kernel<<<(E + 255) / 256, 256>>>(grp, other, E, off, cursor, val);
}

extern "C" void kernel_launch(void* const* d_in, const int* in_sizes, int n_in,
                              void* d_out, int out_size) {
    int wf = -1, gf = -1;
    for (int i = 0; i < n_in; i++) {
        if (wf < 0 && in_sizes[i] == NUx * EMB) wf = i;   // eu
        if (gf < 0 && in_sizes[i] == ERx) gf = i;         // rate_src
    }
    if (wf < 0) wf = 0;
    if (gf < 0) gf = (wf == 0) ? 18 : 0;
    const float* eu        = (const float*)d_in[wf + 0];
    const float* ei        = (const float*)d_in[wf + 1];
    const float* rate_W    = (const float*)d_in[wf + 2];
    const float* rate_b    = (const float*)d_in[wf + 3];
    const float* rate_attn = (const float*)d_in[wf + 4];
    const float* rate_bias = (const float*)d_in[wf + 5];
    const float* rb_W      = (const float*)d_in[wf + 6];
    const float* rb_b      = (const float*)d_in[wf + 7];
    const float* rb_attn   = (const float*)d_in[wf + 8];
    const float* rb_bias   = (const float*)d_in[wf + 9];
    const float* tr_W      = (const float*)d_in[wf + 10];
    const float* tr_b      = (const float*)d_in[wf + 11];
    const float* tr_attn   = (const float*)d_in[wf + 12];
    const float* tr_bias   = (const float*)d_in[wf + 13];
    const float* attW1     = (const float*)d_in[wf + 14];
    const float* attb1     = (const float*)d_in[wf + 15];
    const float* attW2     = (const float*)d_in[wf + 16];
    const float* attb2     = (const float*)d_in[wf + 17];
    const int* rate_src  = (const int*)d_in[gf + 0];
    const int* rate_dst  = (const int*)d_in[gf + 1];
    const int* trust_src = (const int*)d_in[gf + 2];
    const int* trust_dst = (const int*)d_in[gf + 3];
    const int* pos_u     = (const int*)d_in[gf + 4];
    const int* pos_i     = (const int*)d_in[gf + 5];
    const int* neg_u     = (const int*)d_in[gf + 6];
    const int* neg_i     = (const int*)d_in[gf + 7];

    float* hu_all = sym_addr(g_hu_all);
    float* hi_all = sym_addr(g_hi_all);
    float* fsU_rate = sym_addr(g_fsU_rate);
    float* fdU_rb   = sym_addr(g_fdU_rb);
    float* fsU_tr   = sym_addr(g_fsU_tr);
    float* fdU_tr   = sym_addr(g_fdU_tr);
    float* fdI_rate = sym_addr(g_fdI_rate);
    float* fsI_rb   = sym_addr(g_fsI_rb);
    float* pbuf   = sym_addr(g_p);
    float* qbuf   = sym_addr(g_q);
    float* zinf   = sym_addr(g_zinf);
    float* zint   = sym_addr(g_zint);
    float* gate   = sym_addr(g_gate);
    float* sums   = sym_addr(g_sums);
    int* deg      = (int*)sym_addr(g_deg);
    int* cursor   = (int*)sym_addr(g_cursor);
    int* bsum     = (int*)sym_addr(g_bsum);
    int* off_item  = (int*)sym_addr(g_off_item);
    int* off_urate = (int*)sym_addr(g_off_urate);
    int* off_trust = (int*)sym_addr(g_off_trust);
    int* val_item  = (int*)sym_addr(g_val_item);
    int* val_urate = (int*)sym_addr(g_val_urate);
    int* val_trust = (int*)sym_addr(g_val_trust);
    float* out    = (float*)d_out;

    // Build CSRs (layer-invariant)
    build_csr(rate_dst,  rate_src,  ERx, NIx, off_item,  val_item,  deg, cursor, bsum);
    build_csr(rate_src,  rate_dst,  ERx, NUx, off_urate, val_urate, deg, cursor, bsum);
    build_csr(trust_dst, trust_src, ETx, NUx, off_trust, val_trust, deg, cursor, bsum);

    copy_block<<<(NUx * 64 + 255) / 256, 256>>>(eu, hu_all, HALL, NUx * 64);
    copy_block<<<(NIx * 64 + 255) / 256, 256>>>(ei, hi_all, HALL, NIx * 64);

    for (int l = 0; l < NLAYERS; l++) {
        const float* HU = hu_all + l * 64;        // stride HALL
        float* HUo      = hu_all + (l + 1) * 64;
        const float* HI = hi_all + l * 64;
        float* HIo      = hi_all + (l + 1) * 64;

        const float* rW = rate_W + (size_t)l * 2 * 4096;
        const float* rB = rate_b + (size_t)l * 2 * 64;
        const float* bW = rb_W   + (size_t)l * 2 * 4096;
        const float* bB = rb_b   + (size_t)l * 2 * 64;
        const float* tW = tr_W   + (size_t)l * 2 * 4096;
        const float* tB = tr_b   + (size_t)l * 2 * 64;

        // All user-side projections in one launch (shared X transpose)
        GJobs ju;
        ju.m = 4;
        ju.j[0] = { rW,        rB,        fsU_rate };  // rate fc_src
        ju.j[1] = { bW + 4096, bB + 64,   fdU_rb   };  // rb   fc_dst
        ju.j[2] = { tW,        tB,        fsU_tr   };  // tr   fc_src
        ju.j[3] = { tW + 4096, tB + 64,   fdU_tr   };  // tr   fc_dst
        gemm64_multi<<<(NUx + 63) / 64, 256>>>(HU, HALL, NUx, ju);

        // Item-side projections
        GJobs ji;
        ji.m = 2;
        ji.j[0] = { rW + 4096, rB + 64,   fdI_rate };  // rate fc_dst
        ji.j[1] = { bW,        bB,        fsI_rb   };  // rb   fc_src
        ji.j[2] = { nullptr, nullptr, nullptr };
        ji.j[3] = { nullptr, nullptr, nullptr };
        gemm64_multi<<<(NIx + 63) / 64, 256>>>(HI, HALL, NIx, ji);

        // Merged gathers
        GatJobs gj;
        gj.j[0] = { off_item,  val_item,  fsU_rate, fdI_rate,
                    rate_attn + l * 64, rate_bias + l * 64, HI, HALL, HIo, HALL, NIx };
        gj.j[1] = { off_urate, val_urate, fsI_rb,   fdU_rb,
                    rb_attn + l * 64,   rb_bias + l * 64, nullptr, 0, qbuf, 64, NUx };
        gj.j[2] = { off_trust, val_trust, fsU_tr,   fdU_tr,
                    tr_attn + l * 64,   tr_bias + l * 64, nullptr, 0, pbuf, 64, NUx };
        gj.n0 = NIx; gj.n01 = NIx + NUx; gj.ntot = NIx + 2 * NUx;
        gat_gather3<<<(gj.ntot * 32 + 255) / 256, 256>>>(gj);

        // gates
        gate_prep<<<1, 256>>>(attW1 + (size_t)l * 2 * 128 * 128,
                              attb1 + (size_t)l * 2 * 128,
                              attW2 + (size_t)l * 2 * 128,
                              attb2 + (size_t)l * 2, gate);
        cudaMemsetAsync(sums, 0, 4 * sizeof(float));
        z_kernel<<<(NUx + 7) / 8, 256>>>(HU, pbuf, qbuf, gate, zinf, zint, sums, NUx);
        gate_apply<<<(NUx + 7) / 8, 256>>>(HU, HUo, pbuf, qbuf, zinf, zint, sums, NUx);
    }

    pair_kernel<<<(EPx + 7) / 8, 256>>>(pos_u, pos_i, hu_all, hi_all, out, EPx);
    pair_kernel<<<(EPx + 7) / 8, 256>>>(neg_u, neg_i, hu_all, hi_all, out + EPx, EPx);
}